// round 2
// baseline (speedup 1.0000x reference)
#include <cuda_runtime.h>
#include <cuda_bf16.h>

// Shapes
#define BB   8
#define CH   512
#define HH   80
#define WW   80
#define HW   6400          // 80*80
#define CR   32
#define NPOS 160           // H + W

// Scratch (allocation-free rule: __device__ globals)
// g_mean[0] = rgb means, g_mean[1] = t means; layout [(b*512+c)*160 + p], p<80 -> row means (over w), p>=80 -> col means (over h)
__device__ float g_mean[2][BB * CH * NPOS];
// g_s[0]=s_h1, g_s[1]=s_w1, g_s[2]=s_h2, g_s[3]=s_w2; layout [(b*512+o)*80 + (h or w)]
__device__ float g_s[4][BB * CH * 80];

// ---------------------------------------------------------------------------
// Kernel 1: per-(b,c) plane row means and column means for rgb and t.
// grid: (B*CH, 2), block: 256
// ---------------------------------------------------------------------------
__global__ void k_means(const float* __restrict__ rgb, const float* __restrict__ t) {
    __shared__ float sh[HW];
    const int plane = blockIdx.x;                 // b*512 + c
    const float* src = ((blockIdx.y == 0) ? rgb : t) + (size_t)plane * HW;
    for (int i = threadIdx.x; i < HW; i += blockDim.x) sh[i] = src[i];
    __syncthreads();

    float* dst = g_mean[blockIdx.y] + (size_t)plane * NPOS;
    const int tid = threadIdx.x;
    if (tid < 80) {                               // row mean (over w) -> p = h
        float s = 0.f;
        #pragma unroll 8
        for (int w = 0; w < 80; w++) s += sh[tid * 80 + w];
        dst[tid] = s * (1.0f / 80.0f);
    } else if (tid >= 128 && tid < 208) {         // col mean (over h) -> p = 80 + w
        const int w = tid - 128;
        float s = 0.f;
        #pragma unroll 8
        for (int h = 0; h < 80; h++) s += sh[h * 80 + w];
        dst[80 + w] = s * (1.0f / 80.0f);
    }
}

// ---------------------------------------------------------------------------
// Kernel 2: squeeze convs + BN/ReLU + excite convs + sigmoid -> 4 scale maps
// grid: (160, B), block: 256
// ---------------------------------------------------------------------------
__global__ void k_attn(const float* __restrict__ w_r1, const float* __restrict__ w_t1,
                       const float* __restrict__ w_fh1, const float* __restrict__ w_fw1,
                       const float* __restrict__ w_fh2, const float* __restrict__ w_fw2,
                       const float* __restrict__ gam, const float* __restrict__ bet,
                       const float* __restrict__ mu,  const float* __restrict__ var) {
    const int p = blockIdx.x;     // 0..159
    const int b = blockIdx.y;
    __shared__ float ysh[CR];
    __shared__ float zsh[CR];
    const int tid = threadIdx.x;

    // Phase 1: 64 dot products of length 512 (y: 32 via w_r1 on rgb means; z: 32 via w_t1 on t means)
    {
        const int oidx = tid >> 2;       // 0..63
        const int part = tid & 3;        // 4-way split of K=512
        const int cr = oidx & 31;
        const bool isY = (oidx < 32);
        const float* wrow = (isY ? w_r1 : w_t1) + cr * CH + part * 128;
        const float* mrow = g_mean[isY ? 0 : 1] + ((size_t)(b * CH + part * 128)) * NPOS + p;
        float s = 0.f;
        #pragma unroll 8
        for (int c = 0; c < 128; c++) s += wrow[c] * mrow[(size_t)c * NPOS];
        s += __shfl_down_sync(0xffffffffu, s, 1);
        s += __shfl_down_sync(0xffffffffu, s, 2);
        if (part == 0) {
            if (isY) {
                float inv = rsqrtf(var[cr] + 1e-5f);
                float sc = gam[cr] * inv;
                float sf = bet[cr] - gam[cr] * mu[cr] * inv;
                s = s * sc + sf;
            }
            s = fmaxf(s, 0.f);
            (isY ? ysh : zsh)[cr] = s;
        }
    }
    __syncthreads();

    // Phase 2: 512 output channels, two sigmoids each
    const bool isH = (p < 80);
    const float* wf1 = isH ? w_fh1 : w_fw1;
    const float* wf2 = isH ? w_fh2 : w_fw2;
    const int slot1 = isH ? 0 : 1;
    const int slot2 = isH ? 2 : 3;
    const int pp = isH ? p : (p - 80);
    for (int o = tid; o < CH; o += 256) {
        float s1 = 0.f, s2 = 0.f;
        #pragma unroll
        for (int cr = 0; cr < CR; cr++) {
            s1 += wf1[o * CR + cr] * ysh[cr];
            s2 += wf2[o * CR + cr] * zsh[cr];
        }
        s1 = 1.0f / (1.0f + expf(-s1));
        s2 = 1.0f / (1.0f + expf(-s2));
        const size_t idx = ((size_t)(b * CH + o)) * 80 + pp;
        g_s[slot1][idx] = s1;
        g_s[slot2][idx] = s2;
    }
}

// ---------------------------------------------------------------------------
// Kernel 3: fused GEMM (M=51200, N=512, K=1024) + attention-scale epilogue.
// fp32 via packed fma.rn.f32x2 (FFMA2). Tile 128x128x8, 256 threads,
// 8m x 8n per thread as 4 m-pairs x 8 n.
// grid: (400, 4), block: 256
// ---------------------------------------------------------------------------
#define FMA2(d, a, bb) asm("fma.rn.f32x2 %0, %1, %2, %3;" : "=l"(d) : "l"(a), "l"(bb), "l"(d))

__global__ void __launch_bounds__(256) k_main(const float* __restrict__ rgb,
                                              const float* __restrict__ t,
                                              const float* __restrict__ w_fuse,
                                              float* __restrict__ out) {
    __shared__ __align__(16) float  As[8 * 128];   // [k][m]
    __shared__ __align__(16) float2 Bs[8 * 128];   // [k][n], value duplicated in both lanes

    const int tid = threadIdx.x;
    const int mtile = blockIdx.x;            // 0..399 (50 tiles per image)
    const int b = mtile / 50;
    const int hw0 = (mtile % 50) * 128;
    const int n0 = blockIdx.y * 128;

    const int tx = tid & 15;                 // m dimension
    const int ty = tid >> 4;                 // n dimension

    // loader roles
    const int kL = tid >> 5;                 // 0..7
    const int m4 = (tid & 31) * 4;           // 0..124
    const int nL = tid >> 1;                 // 0..127
    const int kq = tid & 1;                  // 0..1

    unsigned long long acc[4][8];
    #pragma unroll
    for (int i = 0; i < 4; i++)
        #pragma unroll
        for (int j = 0; j < 8; j++) acc[i][j] = 0ull;

    float4 ra, rb;
    // fetch tile kb into registers
    {
        const float* src = rgb;
        const int c = kL;  // kb = 0
        ra = *(const float4*)(src + ((size_t)(b * CH + c)) * HW + hw0 + m4);
        rb = *(const float4*)(w_fuse + (size_t)(n0 + nL) * 1024 + kq * 4);
    }

    const unsigned long long* As64 = (const unsigned long long*)As;
    const unsigned long long* Bs64 = (const unsigned long long*)Bs;
    const unsigned long long* Arow = As64 + tx;          // + k*64 + 16*i
    const unsigned long long* Brow = Bs64 + 4 * ty;      // + k*128 + {0..3,64..67}

    for (int kb = 0; kb < 128; kb++) {
        // stage registers -> smem
        *(float4*)&As[kL * 128 + m4] = ra;
        Bs[(kq * 4 + 0) * 128 + nL] = make_float2(rb.x, rb.x);
        Bs[(kq * 4 + 1) * 128 + nL] = make_float2(rb.y, rb.y);
        Bs[(kq * 4 + 2) * 128 + nL] = make_float2(rb.z, rb.z);
        Bs[(kq * 4 + 3) * 128 + nL] = make_float2(rb.w, rb.w);
        __syncthreads();

        // prefetch next tile while computing
        if (kb + 1 < 128) {
            const int kb1 = kb + 1;
            const float* src = (kb1 < 64) ? rgb : t;
            const int c = kb1 * 8 - ((kb1 < 64) ? 0 : 512) + kL;
            ra = *(const float4*)(src + ((size_t)(b * CH + c)) * HW + hw0 + m4);
            rb = *(const float4*)(w_fuse + (size_t)(n0 + nL) * 1024 + kb1 * 8 + kq * 4);
        }

        #pragma unroll
        for (int k = 0; k < 8; k++) {
            const unsigned long long a0 = Arow[k * 64 + 0];
            const unsigned long long a1 = Arow[k * 64 + 16];
            const unsigned long long a2 = Arow[k * 64 + 32];
            const unsigned long long a3 = Arow[k * 64 + 48];
            #pragma unroll
            for (int j = 0; j < 8; j++) {
                const int off = (j & 3) + 64 * (j >> 2);
                const unsigned long long bb = Brow[k * 128 + off];
                FMA2(acc[0][j], a0, bb);
                FMA2(acc[1][j], a1, bb);
                FMA2(acc[2][j], a2, bb);
                FMA2(acc[3][j], a3, bb);
            }
        }
        __syncthreads();
    }

    // Epilogue: scale by (s_h1*s_w1 + s_h2*s_w2) and store
    #pragma unroll
    for (int j = 0; j < 8; j++) {
        const int o = n0 + 4 * ty + (j & 3) + 64 * (j >> 2);
        const size_t sbase = (size_t)(b * CH + o) * 80;
        const float* p1 = g_s[0] + sbase;
        const float* q1 = g_s[1] + sbase;
        const float* p2 = g_s[2] + sbase;
        const float* q2 = g_s[3] + sbase;
        float* obase = out + (size_t)(b * CH + o) * HW;
        #pragma unroll
        for (int i = 0; i < 4; i++) {
            const int m = 2 * tx + 32 * i;
            const int pix = hw0 + m;
            const int h = pix / 80;
            const int w = pix - h * 80;       // pix even => pair (w, w+1) in same row
            union { unsigned long long u; float2 f; } cv;
            cv.u = acc[i][j];
            const float sh1 = p1[h], sh2 = p2[h];
            const float f0 = sh1 * q1[w]     + sh2 * q2[w];
            const float f1 = sh1 * q1[w + 1] + sh2 * q2[w + 1];
            float2 r;
            r.x = cv.f.x * f0;
            r.y = cv.f.y * f1;
            *(float2*)(obase + pix) = r;
        }
    }
}

// ---------------------------------------------------------------------------
extern "C" void kernel_launch(void* const* d_in, const int* in_sizes, int n_in,
                              void* d_out, int out_size) {
    const float* rgb    = (const float*)d_in[0];
    const float* t      = (const float*)d_in[1];
    const float* w_fuse = (const float*)d_in[2];
    const float* w_r1   = (const float*)d_in[3];
    const float* w_t1   = (const float*)d_in[4];
    const float* w_fh1  = (const float*)d_in[5];
    const float* w_fw1  = (const float*)d_in[6];
    const float* w_fh2  = (const float*)d_in[7];
    const float* w_fw2  = (const float*)d_in[8];
    const float* gam    = (const float*)d_in[9];
    const float* bet    = (const float*)d_in[10];
    const float* mu     = (const float*)d_in[11];
    const float* var    = (const float*)d_in[12];
    float* out = (float*)d_out;

    k_means<<<dim3(BB * CH, 2), 256>>>(rgb, t);
    k_attn <<<dim3(NPOS, BB), 256>>>(w_r1, w_t1, w_fh1, w_fw1, w_fh2, w_fw2, gam, bet, mu, var);
    k_main <<<dim3(400, 4), 256>>>(rgb, t, w_fuse, out);
}

// round 4
// speedup vs baseline: 1.8159x; 1.8159x over previous
#include <cuda_runtime.h>
#include <cuda_bf16.h>
#include <cstdint>

// ---------------------------------------------------------------------------
// Shapes
#define BB   8
#define CH   512
#define HW   6400          // 80*80
#define CR   32
#define NPOS 160           // H + W
#define MT   400           // m-tiles of 128 pixels (B*HW/128)
#define KC   32            // main K chunks (32 channels each, of 1024)
#define KC3  16            // lo K chunks (64 channels each)
#define NCHUNK 48          // total K' chunks of 64 bf16

// ---------------------------------------------------------------------------
// __device__ scratch (allocation-free rule)
__device__ float g_mean[2][BB * CH * NPOS];
__device__ float g_s[4][BB * CH * 80];

// Pre-swizzled bf16 operand tiles (SW128, 128-byte rows of 64 bf16):
// A main tile: 128 rows(m) x [a_hi(32ch) | a_lo(32ch)]            = 16KB
// A3 tile    : 128 rows(m) x [a_hi(k..k+32) | a_hi(k+32..k+64)]   = 16KB
// W1 chunk   : 512 rows(o) x [w_hi | w_hi]                        = 64KB
// W3 chunk   : 512 rows(o) x [w_lo(k) | w_lo(k+32)]               = 64KB
__device__ __align__(1024) __nv_bfloat16 g_Amain[(size_t)MT * KC * 8192];
__device__ __align__(1024) __nv_bfloat16 g_A3[(size_t)MT * KC3 * 8192];
__device__ __align__(1024) __nv_bfloat16 g_W1[(size_t)KC * 32768];
__device__ __align__(1024) __nv_bfloat16 g_W3[(size_t)KC3 * 32768];

// ---------------------------------------------------------------------------
__device__ __forceinline__ uint32_t smem_u32(const void* p) {
    uint32_t a;
    asm("{ .reg .u64 t; cvta.to.shared.u64 t, %1; cvt.u32.u64 %0, t; }" : "=r"(a) : "l"(p));
    return a;
}
__device__ __forceinline__ uint32_t sw128(uint32_t off) { return off ^ ((off >> 3) & 0x70); }

__device__ __forceinline__ void cp16(uint32_t dst, const void* src) {
    asm volatile("cp.async.cg.shared.global [%0], [%1], 16;" :: "r"(dst), "l"(src) : "memory");
}
__device__ __forceinline__ void ldsm4(uint32_t r[4], uint32_t addr) {
    asm volatile("ldmatrix.sync.aligned.m8n8.x4.shared.b16 {%0,%1,%2,%3}, [%4];"
                 : "=r"(r[0]), "=r"(r[1]), "=r"(r[2]), "=r"(r[3]) : "r"(addr));
}
__device__ __forceinline__ void mma16816(float c[4], const uint32_t a[4], uint32_t b0, uint32_t b1) {
    asm volatile(
        "mma.sync.aligned.m16n8k16.row.col.f32.bf16.bf16.f32 "
        "{%0,%1,%2,%3}, {%4,%5,%6,%7}, {%8,%9}, {%0,%1,%2,%3};"
        : "+f"(c[0]), "+f"(c[1]), "+f"(c[2]), "+f"(c[3])
        : "r"(a[0]), "r"(a[1]), "r"(a[2]), "r"(a[3]), "r"(b0), "r"(b1));
}

// ---------------------------------------------------------------------------
// Kernel 1: per-(b,c) plane row means and column means for rgb and t.
__global__ void k_means(const float* __restrict__ rgb, const float* __restrict__ t) {
    __shared__ float sh[HW];
    const int plane = blockIdx.x;
    const float* src = ((blockIdx.y == 0) ? rgb : t) + (size_t)plane * HW;
    for (int i = threadIdx.x; i < HW; i += blockDim.x) sh[i] = src[i];
    __syncthreads();

    float* dst = g_mean[blockIdx.y] + (size_t)plane * NPOS;
    const int tid = threadIdx.x;
    if (tid < 80) {
        float s = 0.f;
        #pragma unroll 8
        for (int w = 0; w < 80; w++) s += sh[tid * 80 + w];
        dst[tid] = s * (1.0f / 80.0f);
    } else if (tid >= 128 && tid < 208) {
        const int w = tid - 128;
        float s = 0.f;
        #pragma unroll 8
        for (int h = 0; h < 80; h++) s += sh[h * 80 + w];
        dst[80 + w] = s * (1.0f / 80.0f);
    }
}

// ---------------------------------------------------------------------------
// Kernel 2: squeeze + BN/ReLU + excite + sigmoid -> 4 scale maps
__global__ void k_attn(const float* __restrict__ w_r1, const float* __restrict__ w_t1,
                       const float* __restrict__ w_fh1, const float* __restrict__ w_fw1,
                       const float* __restrict__ w_fh2, const float* __restrict__ w_fw2,
                       const float* __restrict__ gam, const float* __restrict__ bet,
                       const float* __restrict__ mu,  const float* __restrict__ var) {
    const int p = blockIdx.x;
    const int b = blockIdx.y;
    __shared__ float ysh[CR];
    __shared__ float zsh[CR];
    const int tid = threadIdx.x;

    {
        const int oidx = tid >> 2;
        const int part = tid & 3;
        const int cr = oidx & 31;
        const bool isY = (oidx < 32);
        const float* wrow = (isY ? w_r1 : w_t1) + cr * CH + part * 128;
        const float* mrow = g_mean[isY ? 0 : 1] + ((size_t)(b * CH + part * 128)) * NPOS + p;
        float s = 0.f;
        #pragma unroll 8
        for (int c = 0; c < 128; c++) s += wrow[c] * mrow[(size_t)c * NPOS];
        s += __shfl_down_sync(0xffffffffu, s, 1);
        s += __shfl_down_sync(0xffffffffu, s, 2);
        if (part == 0) {
            if (isY) {
                float inv = rsqrtf(var[cr] + 1e-5f);
                float sc = gam[cr] * inv;
                float sf = bet[cr] - gam[cr] * mu[cr] * inv;
                s = s * sc + sf;
            }
            s = fmaxf(s, 0.f);
            (isY ? ysh : zsh)[cr] = s;
        }
    }
    __syncthreads();

    const bool isH = (p < 80);
    const float* wf1 = isH ? w_fh1 : w_fw1;
    const float* wf2 = isH ? w_fh2 : w_fw2;
    const int slot1 = isH ? 0 : 1;
    const int slot2 = isH ? 2 : 3;
    const int pp = isH ? p : (p - 80);
    for (int o = tid; o < CH; o += 256) {
        float s1 = 0.f, s2 = 0.f;
        #pragma unroll
        for (int cr = 0; cr < CR; cr++) {
            s1 += wf1[o * CR + cr] * ysh[cr];
            s2 += wf2[o * CR + cr] * zsh[cr];
        }
        s1 = 1.0f / (1.0f + expf(-s1));
        s2 = 1.0f / (1.0f + expf(-s2));
        const size_t idx = ((size_t)(b * CH + o)) * 80 + pp;
        g_s[slot1][idx] = s1;
        g_s[slot2][idx] = s2;
    }
}

// ---------------------------------------------------------------------------
// Prep A: fp32 [c][hw] -> swizzled bf16 tiles (main hi|lo + A3 hi-pairs)
__global__ void __launch_bounds__(128) k_prepA(const float* __restrict__ rgb,
                                               const float* __restrict__ t) {
    __shared__ float sh[32 * 128];
    const int mtile = blockIdx.x, chunk = blockIdx.y;
    const int b = mtile / 50, hw0 = (mtile % 50) * 128;
    const int tid = threadIdx.x;
    const float* src = (chunk < 16) ? rgb : t;
    const int cbase = (chunk < 16) ? chunk * 32 : chunk * 32 - 512;
    #pragma unroll 4
    for (int i = 0; i < 32; i++)
        sh[i * 128 + tid] = src[((size_t)(b * CH + cbase + i)) * HW + hw0 + tid];
    __syncthreads();

    __nv_bfloat16 hi[32], lo[32];
    #pragma unroll
    for (int j = 0; j < 32; j++) {
        float a = sh[j * 128 + tid];
        hi[j] = __float2bfloat16(a);
        lo[j] = __float2bfloat16(a - __bfloat162float(hi[j]));
    }
    {
        __nv_bfloat16 row[64];
        #pragma unroll
        for (int j = 0; j < 32; j++) { row[j] = hi[j]; row[32 + j] = lo[j]; }
        const uint4* r4 = (const uint4*)row;
        char* dst = (char*)(g_Amain + (size_t)(mtile * KC + chunk) * 8192);
        #pragma unroll
        for (int c = 0; c < 8; c++) {
            uint32_t off = tid * 128 + c * 16;
            *(uint4*)(dst + sw128(off)) = r4[c];
        }
    }
    {
        const uint4* r4 = (const uint4*)hi;
        char* dst = (char*)(g_A3 + (size_t)(mtile * KC3 + (chunk >> 1)) * 8192);
        const uint32_t colbase = (chunk & 1) * 64;
        #pragma unroll
        for (int c = 0; c < 4; c++) {
            uint32_t off = tid * 128 + colbase + c * 16;
            *(uint4*)(dst + sw128(off)) = r4[c];
        }
    }
}

// ---------------------------------------------------------------------------
// Prep W: w_fuse fp32 [o][1024] -> swizzled bf16 W1 ([hi|hi]) and W3 ([lo|lo'])
__global__ void __launch_bounds__(512) k_prepW(const float* __restrict__ w_fuse) {
    const int chunk = blockIdx.x;
    const int o = threadIdx.x;
    float v[32];
    #pragma unroll
    for (int j = 0; j < 32; j++) v[j] = w_fuse[(size_t)o * 1024 + chunk * 32 + j];
    __nv_bfloat16 hi[32], lo[32];
    #pragma unroll
    for (int j = 0; j < 32; j++) {
        hi[j] = __float2bfloat16(v[j]);
        lo[j] = __float2bfloat16(v[j] - __bfloat162float(hi[j]));
    }
    {
        __nv_bfloat16 row[64];
        #pragma unroll
        for (int j = 0; j < 32; j++) { row[j] = hi[j]; row[32 + j] = hi[j]; }
        const uint4* r4 = (const uint4*)row;
        char* dst = (char*)(g_W1 + (size_t)chunk * 32768);
        #pragma unroll
        for (int c = 0; c < 8; c++) {
            uint32_t off = o * 128 + c * 16;
            *(uint4*)(dst + sw128(off)) = r4[c];
        }
    }
    {
        const uint4* r4 = (const uint4*)lo;
        char* dst = (char*)(g_W3 + (size_t)(chunk >> 1) * 32768);
        const uint32_t colbase = (chunk & 1) * 64;
        #pragma unroll
        for (int c = 0; c < 4; c++) {
            uint32_t off = o * 128 + colbase + c * 16;
            *(uint4*)(dst + sw128(off)) = r4[c];
        }
    }
}

// ---------------------------------------------------------------------------
// Kernel 3: HMMA (mma.sync bf16) GEMM. CTA tile 128m x 128n, 48 K-chunks of
// 64 bf16. 8 warps, warp tile 64m x 32n. cp.async double-buffered stages.
// Epilogue: transpose through smem + fused attention scaling, coalesced out.
// grid (400, 4), block 256, dyn smem 67584
#define STAGE 32768

__global__ void __launch_bounds__(256, 2) k_main(float* __restrict__ out) {
    extern __shared__ __align__(16) char smem[];
    const int tid = threadIdx.x, lane = tid & 31, wid = tid >> 5;
    const int mtile = blockIdx.x, b = mtile / 50, hw0 = (mtile % 50) * 128;
    const int n0 = blockIdx.y * 128;
    const int warp_m = (wid & 1) * 64;
    const int warp_n = (wid >> 1) * 32;
    const uint32_t sbase = smem_u32(smem);

    float acc[4][4][4];
    #pragma unroll
    for (int i = 0; i < 4; i++)
        #pragma unroll
        for (int j = 0; j < 4; j++)
            #pragma unroll
            for (int k = 0; k < 4; k++) acc[i][j][k] = 0.f;

    // ldmatrix row offsets (pre-swizzle byte offsets within the 16KB tile)
    uint32_t rowA[4], rowB[2];
    #pragma unroll
    for (int mi = 0; mi < 4; mi++)
        rowA[mi] = (uint32_t)(warp_m + mi * 16 + (lane & 15)) * 128 + (lane >> 4) * 16;
    #pragma unroll
    for (int ni = 0; ni < 2; ni++)
        rowB[ni] = (uint32_t)(warp_n + ni * 16 + (lane & 15)) * 128 + (lane >> 4) * 16;

    // stage loader: 16KB A + 16KB B via 16B cp.async per thread x 4
    auto stage_load = [&](int c, int s) {
        const char* asrc = (c < KC)
            ? (const char*)(g_Amain + (size_t)(mtile * KC + c) * 8192)
            : (const char*)(g_A3 + (size_t)(mtile * KC3 + (c - KC)) * 8192);
        const char* wsrc = (c < KC)
            ? (const char*)(g_W1 + (size_t)c * 32768 + (size_t)n0 * 64)
            : (const char*)(g_W3 + (size_t)(c - KC) * 32768 + (size_t)n0 * 64);
        uint32_t da = sbase + s * STAGE + tid * 16;
        uint32_t db = da + 16384;
        #pragma unroll
        for (int i = 0; i < 4; i++) cp16(da + i * 4096, asrc + tid * 16 + i * 4096);
        #pragma unroll
        for (int i = 0; i < 4; i++) cp16(db + i * 4096, wsrc + tid * 16 + i * 4096);
        asm volatile("cp.async.commit_group;" ::: "memory");
    };

    stage_load(0, 0);
    stage_load(1, 1);

    for (int c = 0; c < NCHUNK; c++) {
        const int s = c & 1;
        if (c < NCHUNK - 2) asm volatile("cp.async.wait_group 1;" ::: "memory");
        else                asm volatile("cp.async.wait_group 0;" ::: "memory");
        __syncthreads();

        const uint32_t Ab = sbase + s * STAGE;
        const uint32_t Bb = Ab + 16384;
        #pragma unroll
        for (int ks = 0; ks < 4; ks++) {
            uint32_t a[4][4], bf[2][4];
            #pragma unroll
            for (int mi = 0; mi < 4; mi++) ldsm4(a[mi], Ab + sw128(rowA[mi] + ks * 32));
            #pragma unroll
            for (int ni = 0; ni < 2; ni++) ldsm4(bf[ni], Bb + sw128(rowB[ni] + ks * 32));
            #pragma unroll
            for (int mi = 0; mi < 4; mi++)
                #pragma unroll
                for (int nj = 0; nj < 4; nj++) {
                    const uint32_t b0 = bf[nj >> 1][(nj & 1) ? 1 : 0];
                    const uint32_t b1 = bf[nj >> 1][(nj & 1) ? 3 : 2];
                    mma16816(acc[mi][nj], a[mi], b0, b1);
                }
        }
        __syncthreads();

        if (c + 2 < NCHUNK) stage_load(c + 2, s);
    }

    // ---- Epilogue: frags -> smem [o_local][m] (132-float rows) ----
    float* cs = (float*)smem;
    #pragma unroll
    for (int mi = 0; mi < 4; mi++)
        #pragma unroll
        for (int nj = 0; nj < 4; nj++) {
            const int ol = warp_n + nj * 8 + (lane & 3) * 2;
            const int m0 = warp_m + mi * 16 + (lane >> 2);
            cs[(ol + 0) * 132 + m0]     = acc[mi][nj][0];
            cs[(ol + 1) * 132 + m0]     = acc[mi][nj][1];
            cs[(ol + 0) * 132 + m0 + 8] = acc[mi][nj][2];
            cs[(ol + 1) * 132 + m0 + 8] = acc[mi][nj][3];
        }
    __syncthreads();

    // ---- Apply attention scales, coalesced store ----
    const size_t ob = (size_t)b * CH;
    const float* s0 = g_s[0];
    const float* s1g = g_s[1];
    const float* s2 = g_s[2];
    const float* s3 = g_s[3];
    const int m = lane * 4;
    const int pix = hw0 + m;
    const int h = pix / 80;
    const int w0 = pix - h * 80;

    #pragma unroll 4
    for (int oi = 0; oi < 16; oi++) {
        const int ol = wid * 16 + oi;
        const int o = n0 + ol;
        const size_t sb2 = (ob + o) * 80;
        float4 v = *(float4*)(cs + ol * 132 + m);
        const float sh1 = s0[sb2 + h], sh2 = s2[sb2 + h];
        v.x *= sh1 * s1g[sb2 + w0]     + sh2 * s3[sb2 + w0];
        v.y *= sh1 * s1g[sb2 + w0 + 1] + sh2 * s3[sb2 + w0 + 1];
        v.z *= sh1 * s1g[sb2 + w0 + 2] + sh2 * s3[sb2 + w0 + 2];
        v.w *= sh1 * s1g[sb2 + w0 + 3] + sh2 * s3[sb2 + w0 + 3];
        *(float4*)(out + (ob + o) * HW + pix) = v;
    }
}

// ---------------------------------------------------------------------------
extern "C" void kernel_launch(void* const* d_in, const int* in_sizes, int n_in,
                              void* d_out, int out_size) {
    const float* rgb    = (const float*)d_in[0];
    const float* t      = (const float*)d_in[1];
    const float* w_fuse = (const float*)d_in[2];
    const float* w_r1   = (const float*)d_in[3];
    const float* w_t1   = (const float*)d_in[4];
    const float* w_fh1  = (const float*)d_in[5];
    const float* w_fw1  = (const float*)d_in[6];
    const float* w_fh2  = (const float*)d_in[7];
    const float* w_fw2  = (const float*)d_in[8];
    const float* gam    = (const float*)d_in[9];
    const float* bet    = (const float*)d_in[10];
    const float* mu     = (const float*)d_in[11];
    const float* var    = (const float*)d_in[12];
    float* out = (float*)d_out;

    cudaFuncSetAttribute(k_main, cudaFuncAttributeMaxDynamicSharedMemorySize, 67584);

    k_means<<<dim3(BB * CH, 2), 256>>>(rgb, t);
    k_prepA<<<dim3(MT, KC), 128>>>(rgb, t);
    k_prepW<<<KC, 512>>>(w_fuse);
    k_attn <<<dim3(NPOS, BB), 256>>>(w_r1, w_t1, w_fh1, w_fw1, w_fh2, w_fw2, gam, bet, mu, var);
    k_main <<<dim3(MT, 4), 256, 67584>>>(out);
}

// round 5
// speedup vs baseline: 1.8346x; 1.0103x over previous
#include <cuda_runtime.h>
#include <cuda_bf16.h>
#include <cstdint>

// ---------------------------------------------------------------------------
// Shapes
#define BB   8
#define CH   512
#define HW   6400          // 80*80
#define CR   32
#define NPOS 160           // H + W
#define MT   400           // m-tiles of 128 pixels (B*HW/128)
#define KC   32            // main K chunks (32 channels each, of 1024)
#define KC3  16            // lo K chunks (64 channels each)
#define NCHUNK 48          // total K' chunks of 64 bf16

// ---------------------------------------------------------------------------
// __device__ scratch (allocation-free rule)
// g_meanT: transposed means, [src][(b*NPOS + p)*CH + c]  (contiguous in c)
__device__ float g_meanT[2][BB * NPOS * CH];
__device__ float g_s[4][BB * CH * 80];

// Pre-swizzled bf16 operand tiles (SW128, 128-byte rows of 64 bf16):
__device__ __align__(1024) __nv_bfloat16 g_Amain[(size_t)MT * KC * 8192];
__device__ __align__(1024) __nv_bfloat16 g_A3[(size_t)MT * KC3 * 8192];
__device__ __align__(1024) __nv_bfloat16 g_W1[(size_t)KC * 32768];
__device__ __align__(1024) __nv_bfloat16 g_W3[(size_t)KC3 * 32768];

// ---------------------------------------------------------------------------
__device__ __forceinline__ uint32_t smem_u32(const void* p) {
    uint32_t a;
    asm("{ .reg .u64 t; cvta.to.shared.u64 t, %1; cvt.u32.u64 %0, t; }" : "=r"(a) : "l"(p));
    return a;
}
__device__ __forceinline__ uint32_t sw128(uint32_t off) { return off ^ ((off >> 3) & 0x70); }

__device__ __forceinline__ void cp16(uint32_t dst, const void* src) {
    asm volatile("cp.async.cg.shared.global [%0], [%1], 16;" :: "r"(dst), "l"(src) : "memory");
}
__device__ __forceinline__ void ldsm4(uint32_t r[4], uint32_t addr) {
    asm volatile("ldmatrix.sync.aligned.m8n8.x4.shared.b16 {%0,%1,%2,%3}, [%4];"
                 : "=r"(r[0]), "=r"(r[1]), "=r"(r[2]), "=r"(r[3]) : "r"(addr));
}
__device__ __forceinline__ void mma16816(float c[4], const uint32_t a[4], uint32_t b0, uint32_t b1) {
    asm volatile(
        "mma.sync.aligned.m16n8k16.row.col.f32.bf16.bf16.f32 "
        "{%0,%1,%2,%3}, {%4,%5,%6,%7}, {%8,%9}, {%0,%1,%2,%3};"
        : "+f"(c[0]), "+f"(c[1]), "+f"(c[2]), "+f"(c[3])
        : "r"(a[0]), "r"(a[1]), "r"(a[2]), "r"(a[3]), "r"(b0), "r"(b1));
}

// ---------------------------------------------------------------------------
// Kernel 1: per-(b,c) plane row/col means -> transposed g_meanT.
// smem rows padded to 81 floats: row-sum bank stride 17 (odd) = conflict-free.
__global__ void k_means(const float* __restrict__ rgb, const float* __restrict__ t) {
    __shared__ float sh[80 * 81];
    const int plane = blockIdx.x;                 // b*512 + c
    const int b = plane >> 9, c = plane & 511;
    const float4* src = (const float4*)(((blockIdx.y == 0) ? rgb : t) + (size_t)plane * HW);
    for (int i = threadIdx.x; i < 1600; i += blockDim.x) {
        float4 v = src[i];
        const int h = i / 20, w = (i % 20) * 4;
        float* r = sh + h * 81 + w;
        r[0] = v.x; r[1] = v.y; r[2] = v.z; r[3] = v.w;
    }
    __syncthreads();

    float* dstT = g_meanT[blockIdx.y] + ((size_t)b * NPOS) * CH + c;
    const int tid = threadIdx.x;
    if (tid < 80) {                               // row mean (over w) -> p = h = tid
        float s = 0.f;
        #pragma unroll 8
        for (int w = 0; w < 80; w++) s += sh[tid * 81 + w];
        dstT[(size_t)tid * CH] = s * (1.0f / 80.0f);
    } else if (tid >= 128 && tid < 208) {         // col mean (over h) -> p = 80 + w
        const int w = tid - 128;
        float s = 0.f;
        #pragma unroll 8
        for (int h = 0; h < 80; h++) s += sh[h * 81 + w];
        dstT[(size_t)(80 + w) * CH] = s * (1.0f / 80.0f);
    }
}

// ---------------------------------------------------------------------------
// Kernel 2: squeeze + BN/ReLU + excite + sigmoid -> 4 scale maps.
// Phase 1 now reads contiguous c from g_meanT (warp-broadcast across oidx).
__global__ void k_attn(const float* __restrict__ w_r1, const float* __restrict__ w_t1,
                       const float* __restrict__ w_fh1, const float* __restrict__ w_fw1,
                       const float* __restrict__ w_fh2, const float* __restrict__ w_fw2,
                       const float* __restrict__ gam, const float* __restrict__ bet,
                       const float* __restrict__ mu,  const float* __restrict__ var) {
    const int p = blockIdx.x;
    const int b = blockIdx.y;
    __shared__ float ysh[CR];
    __shared__ float zsh[CR];
    const int tid = threadIdx.x;

    {
        const int oidx = tid >> 2;       // 0..63
        const int part = tid & 3;        // 4-way K split
        const int cr = oidx & 31;
        const bool isY = (oidx < 32);
        const float* wrow = (isY ? w_r1 : w_t1) + cr * CH + part * 128;
        const float* mrow = g_meanT[isY ? 0 : 1] + ((size_t)(b * NPOS + p)) * CH + part * 128;
        float s = 0.f;
        #pragma unroll 16
        for (int c = 0; c < 128; c++) s += wrow[c] * mrow[c];
        s += __shfl_down_sync(0xffffffffu, s, 1);
        s += __shfl_down_sync(0xffffffffu, s, 2);
        if (part == 0) {
            if (isY) {
                float inv = rsqrtf(var[cr] + 1e-5f);
                float sc = gam[cr] * inv;
                float sf = bet[cr] - gam[cr] * mu[cr] * inv;
                s = s * sc + sf;
            }
            s = fmaxf(s, 0.f);
            (isY ? ysh : zsh)[cr] = s;
        }
    }
    __syncthreads();

    const bool isH = (p < 80);
    const float* wf1 = isH ? w_fh1 : w_fw1;
    const float* wf2 = isH ? w_fh2 : w_fw2;
    const int slot1 = isH ? 0 : 1;
    const int slot2 = isH ? 2 : 3;
    const int pp = isH ? p : (p - 80);
    for (int o = tid; o < CH; o += 256) {
        float s1 = 0.f, s2 = 0.f;
        #pragma unroll
        for (int cr = 0; cr < CR; cr++) {
            s1 += wf1[o * CR + cr] * ysh[cr];
            s2 += wf2[o * CR + cr] * zsh[cr];
        }
        s1 = 1.0f / (1.0f + expf(-s1));
        s2 = 1.0f / (1.0f + expf(-s2));
        const size_t idx = ((size_t)(b * CH + o)) * 80 + pp;
        g_s[slot1][idx] = s1;
        g_s[slot2][idx] = s2;
    }
}

// ---------------------------------------------------------------------------
// Prep A: fp32 [c][hw] -> swizzled bf16 tiles (main hi|lo + A3 hi-pairs)
__global__ void __launch_bounds__(128) k_prepA(const float* __restrict__ rgb,
                                               const float* __restrict__ t) {
    __shared__ float sh[32 * 128];
    const int mtile = blockIdx.x, chunk = blockIdx.y;
    const int b = mtile / 50, hw0 = (mtile % 50) * 128;
    const int tid = threadIdx.x;
    const float* src = (chunk < 16) ? rgb : t;
    const int cbase = (chunk < 16) ? chunk * 32 : chunk * 32 - 512;
    #pragma unroll 4
    for (int i = 0; i < 32; i++)
        sh[i * 128 + tid] = src[((size_t)(b * CH + cbase + i)) * HW + hw0 + tid];
    __syncthreads();

    __nv_bfloat16 hi[32], lo[32];
    #pragma unroll
    for (int j = 0; j < 32; j++) {
        float a = sh[j * 128 + tid];
        hi[j] = __float2bfloat16(a);
        lo[j] = __float2bfloat16(a - __bfloat162float(hi[j]));
    }
    {
        __nv_bfloat16 row[64];
        #pragma unroll
        for (int j = 0; j < 32; j++) { row[j] = hi[j]; row[32 + j] = lo[j]; }
        const uint4* r4 = (const uint4*)row;
        char* dst = (char*)(g_Amain + (size_t)(mtile * KC + chunk) * 8192);
        #pragma unroll
        for (int c = 0; c < 8; c++) {
            uint32_t off = tid * 128 + c * 16;
            *(uint4*)(dst + sw128(off)) = r4[c];
        }
    }
    {
        const uint4* r4 = (const uint4*)hi;
        char* dst = (char*)(g_A3 + (size_t)(mtile * KC3 + (chunk >> 1)) * 8192);
        const uint32_t colbase = (chunk & 1) * 64;
        #pragma unroll
        for (int c = 0; c < 4; c++) {
            uint32_t off = tid * 128 + colbase + c * 16;
            *(uint4*)(dst + sw128(off)) = r4[c];
        }
    }
}

// ---------------------------------------------------------------------------
// Prep W: w_fuse fp32 [o][1024] -> swizzled bf16 W1 ([hi|hi]) and W3 ([lo|lo'])
__global__ void __launch_bounds__(512) k_prepW(const float* __restrict__ w_fuse) {
    const int chunk = blockIdx.x;
    const int o = threadIdx.x;
    float v[32];
    #pragma unroll
    for (int j = 0; j < 32; j++) v[j] = w_fuse[(size_t)o * 1024 + chunk * 32 + j];
    __nv_bfloat16 hi[32], lo[32];
    #pragma unroll
    for (int j = 0; j < 32; j++) {
        hi[j] = __float2bfloat16(v[j]);
        lo[j] = __float2bfloat16(v[j] - __bfloat162float(hi[j]));
    }
    {
        __nv_bfloat16 row[64];
        #pragma unroll
        for (int j = 0; j < 32; j++) { row[j] = hi[j]; row[32 + j] = hi[j]; }
        const uint4* r4 = (const uint4*)row;
        char* dst = (char*)(g_W1 + (size_t)chunk * 32768);
        #pragma unroll
        for (int c = 0; c < 8; c++) {
            uint32_t off = o * 128 + c * 16;
            *(uint4*)(dst + sw128(off)) = r4[c];
        }
    }
    {
        const uint4* r4 = (const uint4*)lo;
        char* dst = (char*)(g_W3 + (size_t)(chunk >> 1) * 32768);
        const uint32_t colbase = (chunk & 1) * 64;
        #pragma unroll
        for (int c = 0; c < 4; c++) {
            uint32_t off = o * 128 + colbase + c * 16;
            *(uint4*)(dst + sw128(off)) = r4[c];
        }
    }
}

// ---------------------------------------------------------------------------
// Kernel 3: HMMA (mma.sync bf16) GEMM. CTA tile 128m x 128n, 48 K-chunks of
// 64 bf16. 8 warps, warp tile 64m x 32n. cp.async double-buffered stages.
// grid (400, 4), block 256, dyn smem 67584
#define STAGE 32768

__global__ void __launch_bounds__(256, 2) k_main(float* __restrict__ out) {
    extern __shared__ __align__(16) char smem[];
    const int tid = threadIdx.x, lane = tid & 31, wid = tid >> 5;
    const int mtile = blockIdx.x, b = mtile / 50, hw0 = (mtile % 50) * 128;
    const int n0 = blockIdx.y * 128;
    const int warp_m = (wid & 1) * 64;
    const int warp_n = (wid >> 1) * 32;
    const uint32_t sbase = smem_u32(smem);

    float acc[4][4][4];
    #pragma unroll
    for (int i = 0; i < 4; i++)
        #pragma unroll
        for (int j = 0; j < 4; j++)
            #pragma unroll
            for (int k = 0; k < 4; k++) acc[i][j][k] = 0.f;

    uint32_t rowA[4], rowB[2];
    #pragma unroll
    for (int mi = 0; mi < 4; mi++)
        rowA[mi] = (uint32_t)(warp_m + mi * 16 + (lane & 15)) * 128 + (lane >> 4) * 16;
    #pragma unroll
    for (int ni = 0; ni < 2; ni++)
        rowB[ni] = (uint32_t)(warp_n + ni * 16 + (lane & 15)) * 128 + (lane >> 4) * 16;

    auto stage_load = [&](int c, int s) {
        const char* asrc = (c < KC)
            ? (const char*)(g_Amain + (size_t)(mtile * KC + c) * 8192)
            : (const char*)(g_A3 + (size_t)(mtile * KC3 + (c - KC)) * 8192);
        const char* wsrc = (c < KC)
            ? (const char*)(g_W1 + (size_t)c * 32768 + (size_t)n0 * 64)
            : (const char*)(g_W3 + (size_t)(c - KC) * 32768 + (size_t)n0 * 64);
        uint32_t da = sbase + s * STAGE + tid * 16;
        uint32_t db = da + 16384;
        #pragma unroll
        for (int i = 0; i < 4; i++) cp16(da + i * 4096, asrc + tid * 16 + i * 4096);
        #pragma unroll
        for (int i = 0; i < 4; i++) cp16(db + i * 4096, wsrc + tid * 16 + i * 4096);
        asm volatile("cp.async.commit_group;" ::: "memory");
    };

    stage_load(0, 0);
    stage_load(1, 1);

    for (int c = 0; c < NCHUNK; c++) {
        const int s = c & 1;
        if (c < NCHUNK - 2) asm volatile("cp.async.wait_group 1;" ::: "memory");
        else                asm volatile("cp.async.wait_group 0;" ::: "memory");
        __syncthreads();

        const uint32_t Ab = sbase + s * STAGE;
        const uint32_t Bb = Ab + 16384;
        #pragma unroll
        for (int ks = 0; ks < 4; ks++) {
            uint32_t a[4][4], bf[2][4];
            #pragma unroll
            for (int mi = 0; mi < 4; mi++) ldsm4(a[mi], Ab + sw128(rowA[mi] + ks * 32));
            #pragma unroll
            for (int ni = 0; ni < 2; ni++) ldsm4(bf[ni], Bb + sw128(rowB[ni] + ks * 32));
            #pragma unroll
            for (int mi = 0; mi < 4; mi++)
                #pragma unroll
                for (int nj = 0; nj < 4; nj++) {
                    const uint32_t b0 = bf[nj >> 1][(nj & 1) ? 1 : 0];
                    const uint32_t b1 = bf[nj >> 1][(nj & 1) ? 3 : 2];
                    mma16816(acc[mi][nj], a[mi], b0, b1);
                }
        }
        __syncthreads();

        if (c + 2 < NCHUNK) stage_load(c + 2, s);
    }

    // ---- Epilogue: frags -> smem [o_local][m] (132-float rows) ----
    float* cs = (float*)smem;
    #pragma unroll
    for (int mi = 0; mi < 4; mi++)
        #pragma unroll
        for (int nj = 0; nj < 4; nj++) {
            const int ol = warp_n + nj * 8 + (lane & 3) * 2;
            const int m0 = warp_m + mi * 16 + (lane >> 2);
            cs[(ol + 0) * 132 + m0]     = acc[mi][nj][0];
            cs[(ol + 1) * 132 + m0]     = acc[mi][nj][1];
            cs[(ol + 0) * 132 + m0 + 8] = acc[mi][nj][2];
            cs[(ol + 1) * 132 + m0 + 8] = acc[mi][nj][3];
        }
    __syncthreads();

    // ---- Apply attention scales, coalesced store ----
    const size_t ob = (size_t)b * CH;
    const float* s0 = g_s[0];
    const float* s1g = g_s[1];
    const float* s2 = g_s[2];
    const float* s3 = g_s[3];
    const int m = lane * 4;
    const int pix = hw0 + m;
    const int h = pix / 80;
    const int w0 = pix - h * 80;

    #pragma unroll 4
    for (int oi = 0; oi < 16; oi++) {
        const int ol = wid * 16 + oi;
        const int o = n0 + ol;
        const size_t sb2 = (ob + o) * 80;
        float4 v = *(float4*)(cs + ol * 132 + m);
        const float sh1 = s0[sb2 + h], sh2 = s2[sb2 + h];
        v.x *= sh1 * s1g[sb2 + w0]     + sh2 * s3[sb2 + w0];
        v.y *= sh1 * s1g[sb2 + w0 + 1] + sh2 * s3[sb2 + w0 + 1];
        v.z *= sh1 * s1g[sb2 + w0 + 2] + sh2 * s3[sb2 + w0 + 2];
        v.w *= sh1 * s1g[sb2 + w0 + 3] + sh2 * s3[sb2 + w0 + 3];
        *(float4*)(out + (ob + o) * HW + pix) = v;
    }
}

// ---------------------------------------------------------------------------
extern "C" void kernel_launch(void* const* d_in, const int* in_sizes, int n_in,
                              void* d_out, int out_size) {
    const float* rgb    = (const float*)d_in[0];
    const float* t      = (const float*)d_in[1];
    const float* w_fuse = (const float*)d_in[2];
    const float* w_r1   = (const float*)d_in[3];
    const float* w_t1   = (const float*)d_in[4];
    const float* w_fh1  = (const float*)d_in[5];
    const float* w_fw1  = (const float*)d_in[6];
    const float* w_fh2  = (const float*)d_in[7];
    const float* w_fw2  = (const float*)d_in[8];
    const float* gam    = (const float*)d_in[9];
    const float* bet    = (const float*)d_in[10];
    const float* mu     = (const float*)d_in[11];
    const float* var    = (const float*)d_in[12];
    float* out = (float*)d_out;

    cudaFuncSetAttribute(k_main, cudaFuncAttributeMaxDynamicSharedMemorySize, 67584);

    k_means<<<dim3(BB * CH, 2), 256>>>(rgb, t);
    k_prepA<<<dim3(MT, KC), 128>>>(rgb, t);
    k_prepW<<<KC, 512>>>(w_fuse);
    k_attn <<<dim3(NPOS, BB), 256>>>(w_r1, w_t1, w_fh1, w_fw1, w_fh2, w_fw2, gam, bet, mu, var);
    k_main <<<dim3(MT, 4), 256, 67584>>>(out);
}

// round 6
// speedup vs baseline: 2.5715x; 1.4016x over previous
#include <cuda_runtime.h>
#include <cuda_bf16.h>
#include <cstdint>

// ---------------------------------------------------------------------------
// Shapes
#define BB   8
#define CH   512
#define HW   6400          // 80*80
#define CR   32
#define NPOS 160           // H + W
#define MT   400           // m-tiles of 128 pixels (B*HW/128)
#define KC   32            // main K chunks (32 channels each, of 1024)
#define KC3  16            // lo K chunks (64 channels each)
#define NCHUNK 48          // total K' chunks of 64 bf16

// ---------------------------------------------------------------------------
// __device__ scratch (allocation-free rule)
// g_meanT: transposed means, [src][(b*NPOS + p)*CH + c]  (contiguous in c)
__device__ float g_meanT[2][BB * NPOS * CH];
// g_yz: squeeze results, [(b*160+p)*64 + idx], idx<32 = y (BN+relu), idx>=32 = z (relu)
__device__ float g_yz[BB * NPOS * 64];
__device__ float g_s[4][BB * CH * 80];

// Pre-swizzled bf16 operand tiles (SW128, 128-byte rows of 64 bf16):
__device__ __align__(1024) __nv_bfloat16 g_Amain[(size_t)MT * KC * 8192];
__device__ __align__(1024) __nv_bfloat16 g_A3[(size_t)MT * KC3 * 8192];
__device__ __align__(1024) __nv_bfloat16 g_W1[(size_t)KC * 32768];
__device__ __align__(1024) __nv_bfloat16 g_W3[(size_t)KC3 * 32768];

// ---------------------------------------------------------------------------
__device__ __forceinline__ uint32_t smem_u32(const void* p) {
    uint32_t a;
    asm("{ .reg .u64 t; cvta.to.shared.u64 t, %1; cvt.u32.u64 %0, t; }" : "=r"(a) : "l"(p));
    return a;
}
__device__ __forceinline__ uint32_t sw128(uint32_t off) { return off ^ ((off >> 3) & 0x70); }

__device__ __forceinline__ void cp16(uint32_t dst, const void* src) {
    asm volatile("cp.async.cg.shared.global [%0], [%1], 16;" :: "r"(dst), "l"(src) : "memory");
}
__device__ __forceinline__ void ldsm4(uint32_t r[4], uint32_t addr) {
    asm volatile("ldmatrix.sync.aligned.m8n8.x4.shared.b16 {%0,%1,%2,%3}, [%4];"
                 : "=r"(r[0]), "=r"(r[1]), "=r"(r[2]), "=r"(r[3]) : "r"(addr));
}
__device__ __forceinline__ void mma16816(float c[4], const uint32_t a[4], uint32_t b0, uint32_t b1) {
    asm volatile(
        "mma.sync.aligned.m16n8k16.row.col.f32.bf16.bf16.f32 "
        "{%0,%1,%2,%3}, {%4,%5,%6,%7}, {%8,%9}, {%0,%1,%2,%3};"
        : "+f"(c[0]), "+f"(c[1]), "+f"(c[2]), "+f"(c[3])
        : "r"(a[0]), "r"(a[1]), "r"(a[2]), "r"(a[3]), "r"(b0), "r"(b1));
}

// ---------------------------------------------------------------------------
// Kernel 1: per-(b,c) plane row/col means -> transposed g_meanT.
__global__ void k_means(const float* __restrict__ rgb, const float* __restrict__ t) {
    __shared__ float sh[80 * 81];
    const int plane = blockIdx.x;                 // b*512 + c
    const int b = plane >> 9, c = plane & 511;
    const float4* src = (const float4*)(((blockIdx.y == 0) ? rgb : t) + (size_t)plane * HW);
    for (int i = threadIdx.x; i < 1600; i += blockDim.x) {
        float4 v = src[i];
        const int h = i / 20, w = (i % 20) * 4;
        float* r = sh + h * 81 + w;
        r[0] = v.x; r[1] = v.y; r[2] = v.z; r[3] = v.w;
    }
    __syncthreads();

    float* dstT = g_meanT[blockIdx.y] + ((size_t)b * NPOS) * CH + c;
    const int tid = threadIdx.x;
    if (tid < 80) {                               // row mean (over w) -> p = h = tid
        float s = 0.f;
        #pragma unroll 8
        for (int w = 0; w < 80; w++) s += sh[tid * 81 + w];
        dstT[(size_t)tid * CH] = s * (1.0f / 80.0f);
    } else if (tid >= 128 && tid < 208) {         // col mean (over h) -> p = 80 + w
        const int w = tid - 128;
        float s = 0.f;
        #pragma unroll 8
        for (int h = 0; h < 80; h++) s += sh[h * 81 + w];
        dstT[(size_t)(80 + w) * CH] = s * (1.0f / 80.0f);
    }
}

// ---------------------------------------------------------------------------
// Kernel 2a: squeeze convs + BN/ReLU. One block per (b,p). Lane-coalesced
// weight reads (c = lane + 32*i), means staged in smem, warp-shfl reduction.
// grid 1280, block 128
__global__ void __launch_bounds__(128) k_squeeze(
        const float* __restrict__ w_r1, const float* __restrict__ w_t1,
        const float* __restrict__ gam, const float* __restrict__ bet,
        const float* __restrict__ mu,  const float* __restrict__ var) {
    const int bp = blockIdx.x;              // b*160 + p
    __shared__ float msh[1024];             // [0:512) rgb means, [512:1024) t means
    const int tid = threadIdx.x;
    const float* m0 = g_meanT[0] + (size_t)bp * CH;
    const float* m1 = g_meanT[1] + (size_t)bp * CH;
    #pragma unroll
    for (int i = 0; i < 4; i++) msh[tid + 128 * i] = m0[tid + 128 * i];
    #pragma unroll
    for (int i = 0; i < 4; i++) msh[512 + tid + 128 * i] = m1[tid + 128 * i];
    __syncthreads();

    const int wid = tid >> 5, lane = tid & 31;
    #pragma unroll
    for (int j = 0; j < 16; j++) {
        const int idx = wid * 16 + j;       // 0..63
        const int cr = idx & 31;
        const bool isY = (idx < 32);
        const float* wrow = (isY ? w_r1 : w_t1) + cr * CH;
        const float* mm = msh + (isY ? 0 : 512);
        float s = 0.f;
        #pragma unroll
        for (int i = 0; i < 16; i++) s += wrow[lane + 32 * i] * mm[lane + 32 * i];
        #pragma unroll
        for (int off = 16; off; off >>= 1) s += __shfl_xor_sync(0xffffffffu, s, off);
        if (lane == 0) {
            if (isY) {
                const float inv = rsqrtf(var[cr] + 1e-5f);
                s = s * (gam[cr] * inv) + (bet[cr] - gam[cr] * mu[cr] * inv);
            }
            g_yz[(size_t)bp * 64 + idx] = fmaxf(s, 0.f);
        }
    }
}

// ---------------------------------------------------------------------------
// Kernel 2b: excite convs + sigmoid -> 4 scale maps, all-smem compute.
// grid (8 otile, 8 b), block 320, dyn smem 73984
__global__ void __launch_bounds__(320) k_excite(
        const float* __restrict__ w_fh1, const float* __restrict__ w_fw1,
        const float* __restrict__ w_fh2, const float* __restrict__ w_fw2) {
    extern __shared__ float es[];
    float* sy = es;                    // [64][161] transposed y/z
    float* wh1 = es + 64 * 161;        // [64][32] each
    float* ww1 = wh1 + 2048;
    float* wh2 = ww1 + 2048;
    float* ww2 = wh2 + 2048;

    const int otile = blockIdx.x, b = blockIdx.y;
    const int tid = threadIdx.x;

    // load y/z for this b, transposing [p][idx] -> [idx][p]
    const float* src = g_yz + (size_t)b * NPOS * 64;
    for (int i = tid; i < NPOS * 64; i += 320) {
        const int p = i >> 6, idx = i & 63;
        sy[idx * 161 + p] = src[i];
    }
    // load 64x32 weight blocks (contiguous, coalesced)
    const int wbase = otile * 64 * CR;
    for (int i = tid; i < 2048; i += 320) {
        wh1[i] = w_fh1[wbase + i];
        ww1[i] = w_fw1[wbase + i];
        wh2[i] = w_fh2[wbase + i];
        ww2[i] = w_fw2[wbase + i];
    }
    __syncthreads();

    const int p = tid % 80;            // h or w coordinate
    const int osub = tid / 80;         // 0..3
    #pragma unroll 4
    for (int i = 0; i < 16; i++) {
        const int ol = osub * 16 + i;
        const int o = otile * 64 + ol;
        float a1 = 0.f, a2 = 0.f, a3 = 0.f, a4 = 0.f;
        #pragma unroll
        for (int cr = 0; cr < CR; cr++) {
            const float yh = sy[cr * 161 + p];
            const float yw = sy[cr * 161 + 80 + p];
            const float zh = sy[(32 + cr) * 161 + p];
            const float zw = sy[(32 + cr) * 161 + 80 + p];
            a1 += wh1[ol * CR + cr] * yh;
            a2 += ww1[ol * CR + cr] * yw;
            a3 += wh2[ol * CR + cr] * zh;
            a4 += ww2[ol * CR + cr] * zw;
        }
        const size_t idx = ((size_t)(b * CH + o)) * 80 + p;
        g_s[0][idx] = 1.0f / (1.0f + expf(-a1));
        g_s[1][idx] = 1.0f / (1.0f + expf(-a2));
        g_s[2][idx] = 1.0f / (1.0f + expf(-a3));
        g_s[3][idx] = 1.0f / (1.0f + expf(-a4));
    }
}

// ---------------------------------------------------------------------------
// Prep A: fp32 [c][hw] -> swizzled bf16 tiles (main hi|lo + A3 hi-pairs)
__global__ void __launch_bounds__(128) k_prepA(const float* __restrict__ rgb,
                                               const float* __restrict__ t) {
    __shared__ float sh[32 * 128];
    const int mtile = blockIdx.x, chunk = blockIdx.y;
    const int b = mtile / 50, hw0 = (mtile % 50) * 128;
    const int tid = threadIdx.x;
    const float* src = (chunk < 16) ? rgb : t;
    const int cbase = (chunk < 16) ? chunk * 32 : chunk * 32 - 512;
    #pragma unroll 4
    for (int i = 0; i < 32; i++)
        sh[i * 128 + tid] = src[((size_t)(b * CH + cbase + i)) * HW + hw0 + tid];
    __syncthreads();

    __nv_bfloat16 hi[32], lo[32];
    #pragma unroll
    for (int j = 0; j < 32; j++) {
        float a = sh[j * 128 + tid];
        hi[j] = __float2bfloat16(a);
        lo[j] = __float2bfloat16(a - __bfloat162float(hi[j]));
    }
    {
        __nv_bfloat16 row[64];
        #pragma unroll
        for (int j = 0; j < 32; j++) { row[j] = hi[j]; row[32 + j] = lo[j]; }
        const uint4* r4 = (const uint4*)row;
        char* dst = (char*)(g_Amain + (size_t)(mtile * KC + chunk) * 8192);
        #pragma unroll
        for (int c = 0; c < 8; c++) {
            uint32_t off = tid * 128 + c * 16;
            *(uint4*)(dst + sw128(off)) = r4[c];
        }
    }
    {
        const uint4* r4 = (const uint4*)hi;
        char* dst = (char*)(g_A3 + (size_t)(mtile * KC3 + (chunk >> 1)) * 8192);
        const uint32_t colbase = (chunk & 1) * 64;
        #pragma unroll
        for (int c = 0; c < 4; c++) {
            uint32_t off = tid * 128 + colbase + c * 16;
            *(uint4*)(dst + sw128(off)) = r4[c];
        }
    }
}

// ---------------------------------------------------------------------------
// Prep W: w_fuse fp32 [o][1024] -> swizzled bf16 W1 ([hi|hi]) and W3 ([lo|lo'])
__global__ void __launch_bounds__(512) k_prepW(const float* __restrict__ w_fuse) {
    const int chunk = blockIdx.x;
    const int o = threadIdx.x;
    float v[32];
    #pragma unroll
    for (int j = 0; j < 32; j++) v[j] = w_fuse[(size_t)o * 1024 + chunk * 32 + j];
    __nv_bfloat16 hi[32], lo[32];
    #pragma unroll
    for (int j = 0; j < 32; j++) {
        hi[j] = __float2bfloat16(v[j]);
        lo[j] = __float2bfloat16(v[j] - __bfloat162float(hi[j]));
    }
    {
        __nv_bfloat16 row[64];
        #pragma unroll
        for (int j = 0; j < 32; j++) { row[j] = hi[j]; row[32 + j] = hi[j]; }
        const uint4* r4 = (const uint4*)row;
        char* dst = (char*)(g_W1 + (size_t)chunk * 32768);
        #pragma unroll
        for (int c = 0; c < 8; c++) {
            uint32_t off = o * 128 + c * 16;
            *(uint4*)(dst + sw128(off)) = r4[c];
        }
    }
    {
        const uint4* r4 = (const uint4*)lo;
        char* dst = (char*)(g_W3 + (size_t)(chunk >> 1) * 32768);
        const uint32_t colbase = (chunk & 1) * 64;
        #pragma unroll
        for (int c = 0; c < 4; c++) {
            uint32_t off = o * 128 + colbase + c * 16;
            *(uint4*)(dst + sw128(off)) = r4[c];
        }
    }
}

// ---------------------------------------------------------------------------
// Kernel 3: HMMA (mma.sync bf16) GEMM. CTA tile 128m x 128n, 48 K-chunks of
// 64 bf16. 8 warps, warp tile 64m x 32n. cp.async double-buffered stages.
// grid (400, 4), block 256, dyn smem 67584
#define STAGE 32768

__global__ void __launch_bounds__(256, 2) k_main(float* __restrict__ out) {
    extern __shared__ __align__(16) char smem[];
    const int tid = threadIdx.x, lane = tid & 31, wid = tid >> 5;
    const int mtile = blockIdx.x, b = mtile / 50, hw0 = (mtile % 50) * 128;
    const int n0 = blockIdx.y * 128;
    const int warp_m = (wid & 1) * 64;
    const int warp_n = (wid >> 1) * 32;
    const uint32_t sbase = smem_u32(smem);

    float acc[4][4][4];
    #pragma unroll
    for (int i = 0; i < 4; i++)
        #pragma unroll
        for (int j = 0; j < 4; j++)
            #pragma unroll
            for (int k = 0; k < 4; k++) acc[i][j][k] = 0.f;

    uint32_t rowA[4], rowB[2];
    #pragma unroll
    for (int mi = 0; mi < 4; mi++)
        rowA[mi] = (uint32_t)(warp_m + mi * 16 + (lane & 15)) * 128 + (lane >> 4) * 16;
    #pragma unroll
    for (int ni = 0; ni < 2; ni++)
        rowB[ni] = (uint32_t)(warp_n + ni * 16 + (lane & 15)) * 128 + (lane >> 4) * 16;

    auto stage_load = [&](int c, int s) {
        const char* asrc = (c < KC)
            ? (const char*)(g_Amain + (size_t)(mtile * KC + c) * 8192)
            : (const char*)(g_A3 + (size_t)(mtile * KC3 + (c - KC)) * 8192);
        const char* wsrc = (c < KC)
            ? (const char*)(g_W1 + (size_t)c * 32768 + (size_t)n0 * 64)
            : (const char*)(g_W3 + (size_t)(c - KC) * 32768 + (size_t)n0 * 64);
        uint32_t da = sbase + s * STAGE + tid * 16;
        uint32_t db = da + 16384;
        #pragma unroll
        for (int i = 0; i < 4; i++) cp16(da + i * 4096, asrc + tid * 16 + i * 4096);
        #pragma unroll
        for (int i = 0; i < 4; i++) cp16(db + i * 4096, wsrc + tid * 16 + i * 4096);
        asm volatile("cp.async.commit_group;" ::: "memory");
    };

    stage_load(0, 0);
    stage_load(1, 1);

    for (int c = 0; c < NCHUNK; c++) {
        const int s = c & 1;
        if (c < NCHUNK - 2) asm volatile("cp.async.wait_group 1;" ::: "memory");
        else                asm volatile("cp.async.wait_group 0;" ::: "memory");
        __syncthreads();

        const uint32_t Ab = sbase + s * STAGE;
        const uint32_t Bb = Ab + 16384;
        #pragma unroll
        for (int ks = 0; ks < 4; ks++) {
            uint32_t a[4][4], bf[2][4];
            #pragma unroll
            for (int mi = 0; mi < 4; mi++) ldsm4(a[mi], Ab + sw128(rowA[mi] + ks * 32));
            #pragma unroll
            for (int ni = 0; ni < 2; ni++) ldsm4(bf[ni], Bb + sw128(rowB[ni] + ks * 32));
            #pragma unroll
            for (int mi = 0; mi < 4; mi++)
                #pragma unroll
                for (int nj = 0; nj < 4; nj++) {
                    const uint32_t b0 = bf[nj >> 1][(nj & 1) ? 1 : 0];
                    const uint32_t b1 = bf[nj >> 1][(nj & 1) ? 3 : 2];
                    mma16816(acc[mi][nj], a[mi], b0, b1);
                }
        }
        __syncthreads();

        if (c + 2 < NCHUNK) stage_load(c + 2, s);
    }

    // ---- Epilogue: frags -> smem [o_local][m] (132-float rows) ----
    float* cs = (float*)smem;
    #pragma unroll
    for (int mi = 0; mi < 4; mi++)
        #pragma unroll
        for (int nj = 0; nj < 4; nj++) {
            const int ol = warp_n + nj * 8 + (lane & 3) * 2;
            const int m0 = warp_m + mi * 16 + (lane >> 2);
            cs[(ol + 0) * 132 + m0]     = acc[mi][nj][0];
            cs[(ol + 1) * 132 + m0]     = acc[mi][nj][1];
            cs[(ol + 0) * 132 + m0 + 8] = acc[mi][nj][2];
            cs[(ol + 1) * 132 + m0 + 8] = acc[mi][nj][3];
        }
    __syncthreads();

    // ---- Apply attention scales, coalesced store ----
    const size_t ob = (size_t)b * CH;
    const float* s0 = g_s[0];
    const float* s1g = g_s[1];
    const float* s2 = g_s[2];
    const float* s3 = g_s[3];
    const int m = lane * 4;
    const int pix = hw0 + m;
    const int h = pix / 80;
    const int w0 = pix - h * 80;

    #pragma unroll 4
    for (int oi = 0; oi < 16; oi++) {
        const int ol = wid * 16 + oi;
        const int o = n0 + ol;
        const size_t sb2 = (ob + o) * 80;
        float4 v = *(float4*)(cs + ol * 132 + m);
        const float sh1 = s0[sb2 + h], sh2 = s2[sb2 + h];
        v.x *= sh1 * s1g[sb2 + w0]     + sh2 * s3[sb2 + w0];
        v.y *= sh1 * s1g[sb2 + w0 + 1] + sh2 * s3[sb2 + w0 + 1];
        v.z *= sh1 * s1g[sb2 + w0 + 2] + sh2 * s3[sb2 + w0 + 2];
        v.w *= sh1 * s1g[sb2 + w0 + 3] + sh2 * s3[sb2 + w0 + 3];
        *(float4*)(out + (ob + o) * HW + pix) = v;
    }
}

// ---------------------------------------------------------------------------
extern "C" void kernel_launch(void* const* d_in, const int* in_sizes, int n_in,
                              void* d_out, int out_size) {
    const float* rgb    = (const float*)d_in[0];
    const float* t      = (const float*)d_in[1];
    const float* w_fuse = (const float*)d_in[2];
    const float* w_r1   = (const float*)d_in[3];
    const float* w_t1   = (const float*)d_in[4];
    const float* w_fh1  = (const float*)d_in[5];
    const float* w_fw1  = (const float*)d_in[6];
    const float* w_fh2  = (const float*)d_in[7];
    const float* w_fw2  = (const float*)d_in[8];
    const float* gam    = (const float*)d_in[9];
    const float* bet    = (const float*)d_in[10];
    const float* mu     = (const float*)d_in[11];
    const float* var    = (const float*)d_in[12];
    float* out = (float*)d_out;

    cudaFuncSetAttribute(k_main, cudaFuncAttributeMaxDynamicSharedMemorySize, 67584);
    cudaFuncSetAttribute(k_excite, cudaFuncAttributeMaxDynamicSharedMemorySize, 73984);

    k_means<<<dim3(BB * CH, 2), 256>>>(rgb, t);
    k_squeeze<<<BB * NPOS, 128>>>(w_r1, w_t1, gam, bet, mu, var);
    k_excite<<<dim3(8, BB), 320, 73984>>>(w_fh1, w_fw1, w_fh2, w_fw2);
    k_prepA<<<dim3(MT, KC), 128>>>(rgb, t);
    k_prepW<<<KC, 512>>>(w_fuse);
    k_main <<<dim3(MT, 4), 256, 67584>>>(out);
}